// round 1
// baseline (speedup 1.0000x reference)
#include <cuda_runtime.h>

// DNAShapeNet fused kernel: 4x (Conv1d + ReLU + BN) + per-position MLP.
// B=128, S=8192, channels 4->32->32->32->32, kernels {3,3,5,7}, MLP 32->16->1.
// Fully fused in shared memory: one block = one (batch, 512-pos tile) with
// 7-element halo each side. fp32 FFMA throughout (FMA-pipe bound baseline).

#define BATCH    128
#define SEQ      8192
#define TSIZE    512           // output positions per block
#define NTHREADS 512
#define WPAD     544           // smem row stride (floats) for activation buffers
#define HALO     7             // 1+1+2+3

// ---- smem layout (float offsets) ----
#define OFF_BUFA 0                       // 32*544 = 17408
#define OFF_BUFB (OFF_BUFA + 32*WPAD)    // 17408
#define OFF_W0   (OFF_BUFB + 32*WPAD)    // 34816 ; 32*4*3   = 384
#define OFF_W1   (OFF_W0 + 384)          // 35200 ; 32*32*3  = 3072
#define OFF_W2   (OFF_W1 + 3072)         // 38272 ; 32*32*5  = 5120
#define OFF_W3   (OFF_W2 + 5120)         // 43392 ; 32*32*7  = 7168
#define OFF_SC   (OFF_W3 + 7168)         // 50560 ; 4*32
#define OFF_SH   (OFF_SC + 128)          // 50688
#define OFF_BI   (OFF_SH + 128)          // 50816
#define OFF_FW1  (OFF_BI + 128)          // 50944 ; 16*32
#define OFF_FB1  (OFF_FW1 + 512)         // 51456
#define OFF_FW2  (OFF_FB1 + 16)          // 51472
#define OFF_FB2  (OFF_FW2 + 16)          // 51488
#define SMEM_FLOATS (OFF_FB2 + 1)        // 51489
#define SMEM_BYTES  (SMEM_FLOATS * 4)    // 205956

struct Ptrs {
    const float* x;
    const float* w[4];
    const float* b[4];
    const float* g[4];
    const float* bb[4];
    const float* rm[4];
    const float* rv[4];
    const float* fw1;
    const float* fb1;
    const float* fw2;
    const float* fb2;
};

// One conv+ReLU+BN layer computed from smem -> smem.
// Thread (co, j) computes out channel co at 33 contiguous positions
// starting at OFF + j*33 (lane stride 33 words => conflict-free LDS).
// Positions whose absolute sequence index falls outside [0,S) are written as 0
// to reproduce the reference's per-layer zero padding.
template <int CIN, int K, int WOUT, int LOFF>
__device__ __forceinline__ void conv_layer(
    const float* __restrict__ sin, float* __restrict__ sout,
    const float* __restrict__ wgt,
    const float* __restrict__ sc, const float* __restrict__ sh,
    const float* __restrict__ bi,
    int co, int j, int seq_base)
{
    constexpr int STRIP = 33;
    constexpr int CH = 11;            // 3 chunks of 11
    constexpr int H = K / 2;

    float acc[STRIP];
#pragma unroll
    for (int i = 0; i < STRIP; ++i) acc[i] = 0.f;

    const float* wrow = wgt + co * (CIN * K);

#pragma unroll 1
    for (int cin = 0; cin < CIN; ++cin) {
        float w[K];
#pragma unroll
        for (int t = 0; t < K; ++t) w[t] = wrow[cin * K + t];

        const float* xin = sin + cin * WPAD + (LOFF - H) + j * STRIP;

#pragma unroll
        for (int c0 = 0; c0 < STRIP; c0 += CH) {
            float xv[CH + K - 1];
#pragma unroll
            for (int i = 0; i < CH + K - 1; ++i) xv[i] = xin[c0 + i];
#pragma unroll
            for (int t = 0; t < K; ++t) {
#pragma unroll
                for (int p = 0; p < CH; ++p)
                    acc[c0 + p] = fmaf(w[t], xv[p + t], acc[c0 + p]);
            }
        }
    }

    const float scale = sc[co];
    const float shift = sh[co];
    const float bias  = bi[co];
    float* orow = sout + co * WPAD;

#pragma unroll
    for (int i = 0; i < STRIP; ++i) {
        int pl = j * STRIP + i;
        if (pl < WOUT) {
            int u = LOFF + pl;
            int seq = seq_base + u;
            float y = fmaxf(acc[i] + bias, 0.f);
            float v = (seq >= 0 && seq < SEQ) ? fmaf(y, scale, shift) : 0.f;
            orow[u] = v;
        }
    }
}

__global__ void __launch_bounds__(NTHREADS, 1)
dna_fused_kernel(Ptrs P, float* __restrict__ out)
{
    extern __shared__ float sm[];
    const int tid = threadIdx.x;
    const int ts  = blockIdx.x * TSIZE;   // tile start in sequence
    const int b   = blockIdx.y;           // batch
    const int seq_base = ts - HALO;       // buffer index u=0 <-> seq ts-7

    float* bufA = sm + OFF_BUFA;
    float* bufB = sm + OFF_BUFB;
    float* sW[4] = { sm + OFF_W0, sm + OFF_W1, sm + OFF_W2, sm + OFF_W3 };
    float* sSC = sm + OFF_SC;
    float* sSH = sm + OFF_SH;
    float* sBI = sm + OFF_BI;
    float* sFW1 = sm + OFF_FW1;
    float* sFB1 = sm + OFF_FB1;
    float* sFW2 = sm + OFF_FW2;
    float* sFB2 = sm + OFF_FB2;

    // ---- cooperative parameter loads ----
    const int wn[4] = { 32 * 4 * 3, 32 * 32 * 3, 32 * 32 * 5, 32 * 32 * 7 };
#pragma unroll
    for (int l = 0; l < 4; ++l)
        for (int i = tid; i < wn[l]; i += NTHREADS) sW[l][i] = P.w[l][i];

    for (int i = tid; i < 16 * 32; i += NTHREADS) sFW1[i] = P.fw1[i];
    if (tid < 16) { sFB1[tid] = P.fb1[tid]; sFW2[tid] = P.fw2[tid]; }
    if (tid == 0) sFB2[0] = P.fb2[0];

    if (tid < 128) {
        int l = tid >> 5, c = tid & 31;
        float inv = P.g[l][c] * rsqrtf(P.rv[l][c] + 1e-5f);
        sSC[tid] = inv;
        sSH[tid] = P.bb[l][c] - P.rm[l][c] * inv;
        sBI[tid] = P.b[l][c];
    }

    // ---- input tile (4 channels, width 526) with zero halo ----
    constexpr int WIN = TSIZE + 2 * HALO;   // 526
    for (int idx = tid; idx < 4 * WIN; idx += NTHREADS) {
        int cin = idx / WIN;
        int u = idx - cin * WIN;
        int seq = seq_base + u;
        bufA[cin * WPAD + u] =
            (seq >= 0 && seq < SEQ) ? P.x[(b * 4 + cin) * SEQ + seq] : 0.f;
    }
    __syncthreads();

    const int co = tid >> 4;
    const int j  = tid & 15;

    // layer widths: 524 @ off 1 -> 522 @ off 2 -> 518 @ off 4 -> 512 @ off 7
    conv_layer<4, 3, 524, 1>(bufA, bufB, sW[0], sSC +  0, sSH +  0, sBI +  0, co, j, seq_base);
    __syncthreads();
    conv_layer<32, 3, 522, 2>(bufB, bufA, sW[1], sSC + 32, sSH + 32, sBI + 32, co, j, seq_base);
    __syncthreads();
    conv_layer<32, 5, 518, 4>(bufA, bufB, sW[2], sSC + 64, sSH + 64, sBI + 64, co, j, seq_base);
    __syncthreads();
    conv_layer<32, 7, 512, 7>(bufB, bufA, sW[3], sSC + 96, sSH + 96, sBI + 96, co, j, seq_base);
    __syncthreads();

    // ---- per-position MLP: 32 -> 16 (ReLU) -> 1 ; one thread per position ----
    float yc[32];
#pragma unroll
    for (int c = 0; c < 32; ++c) yc[c] = bufA[c * WPAD + HALO + tid];

    float o = sFB2[0];
#pragma unroll
    for (int i = 0; i < 16; ++i) {
        float h = sFB1[i];
#pragma unroll
        for (int c = 0; c < 32; ++c) h = fmaf(sFW1[i * 32 + c], yc[c], h);
        o = fmaf(fmaxf(h, 0.f), sFW2[i], o);
    }
    out[b * SEQ + ts + tid] = o;
}

extern "C" void kernel_launch(void* const* d_in, const int* in_sizes, int n_in,
                              void* d_out, int out_size)
{
    Ptrs P;
    P.x = (const float*)d_in[0];
    for (int l = 0; l < 4; ++l) {
        P.w[l]  = (const float*)d_in[1 + 6 * l];
        P.b[l]  = (const float*)d_in[2 + 6 * l];
        P.g[l]  = (const float*)d_in[3 + 6 * l];
        P.bb[l] = (const float*)d_in[4 + 6 * l];
        P.rm[l] = (const float*)d_in[5 + 6 * l];
        P.rv[l] = (const float*)d_in[6 + 6 * l];
    }
    P.fw1 = (const float*)d_in[25];
    P.fb1 = (const float*)d_in[26];
    P.fw2 = (const float*)d_in[27];
    P.fb2 = (const float*)d_in[28];

    cudaFuncSetAttribute(dna_fused_kernel,
                         cudaFuncAttributeMaxDynamicSharedMemorySize, SMEM_BYTES);

    dim3 grid(SEQ / TSIZE, BATCH);
    dna_fused_kernel<<<grid, NTHREADS, SMEM_BYTES>>>(P, (float*)d_out);
}